// round 16
// baseline (speedup 1.0000x reference)
#include <cuda_runtime.h>
#include <cuda_fp16.h>
#include <math.h>
#include <stdint.h>

#define BB   2
#define TT   1024
#define EE   1024
#define HH   16
#define HD   64
#define LL   8
#define FF_  4096
#define VV   32000
#define MROWS (BB*TT)          // 2048
#define NSEG (VV/64)           // 500

// ---------------- scratch ----------------
__device__ float  g_x  [MROWS*EE];
__device__ __half g_h  [MROWS*EE];
__device__ __half g_q  [MROWS*EE];
__device__ __half g_k  [MROWS*EE];
__device__ __half g_v  [MROWS*EE];
__device__ __half g_o  [MROWS*EE];
__device__ __half g_ff [MROWS*FF_];
__device__ float  g_rowloss[MROWS];
__device__ float2 g_lpart[(size_t)MROWS*NSEG];   // 8 MB loss partials
__device__ __half g_whq[LL*EE*EE];
__device__ __half g_whk[LL*EE*EE];
__device__ __half g_whv[LL*EE*EE];
__device__ __half g_who[LL*EE*EE];
__device__ __half g_wh1[LL*EE*FF_];
__device__ __half g_wh2[LL*FF_*EE];
__device__ __half g_whlm[(size_t)EE*VV];

// ---------------- helpers ----------------
__device__ __forceinline__ void mma_f16(float* d, const uint32_t* a, const uint32_t* b) {
    asm volatile(
        "mma.sync.aligned.m16n8k16.row.col.f32.f16.f16.f32 "
        "{%0,%1,%2,%3}, {%4,%5,%6,%7}, {%8,%9}, {%0,%1,%2,%3};"
        : "+f"(d[0]), "+f"(d[1]), "+f"(d[2]), "+f"(d[3])
        : "r"(a[0]), "r"(a[1]), "r"(a[2]), "r"(a[3]), "r"(b[0]), "r"(b[1]));
}
__device__ __forceinline__ void ldsm4(uint32_t* r, uint32_t addr) {
    asm volatile("ldmatrix.sync.aligned.m8n8.x4.shared.b16 {%0,%1,%2,%3}, [%4];"
        : "=r"(r[0]), "=r"(r[1]), "=r"(r[2]), "=r"(r[3]) : "r"(addr));
}
__device__ __forceinline__ void ldsm4t(uint32_t* r, uint32_t addr) {
    asm volatile("ldmatrix.sync.aligned.m8n8.x4.trans.shared.b16 {%0,%1,%2,%3}, [%4];"
        : "=r"(r[0]), "=r"(r[1]), "=r"(r[2]), "=r"(r[3]) : "r"(addr));
}
__device__ __forceinline__ uint32_t smem_u32(const void* p) {
    return (uint32_t)__cvta_generic_to_shared(p);
}
__device__ __forceinline__ void cp16h(__half* s, const __half* g) {
    uint32_t sa = smem_u32(s);
    asm volatile("cp.async.ca.shared.global [%0], [%1], 16;" :: "r"(sa), "l"(g));
}
#define CP_COMMIT() asm volatile("cp.async.commit_group;")

// MUFU-based exp
__device__ __forceinline__ float mexp(float x) {
    float r;
    asm("ex2.approx.f32 %0, %1;" : "=f"(r) : "f"(x * 1.44269504f));
    return r;
}
__device__ __forceinline__ uint32_t h2pack(float a, float b) {
    __half2 h = __floats2half2_rn(a, b);
    return *(uint32_t*)&h;
}

// ---------------- streaming fp32 -> fp16 convert ----------------
__global__ void conv_h2(const float4* __restrict__ in, uint4* __restrict__ out, int n8)
{
    int i = blockIdx.x * blockDim.x + threadIdx.x;
    int stride = gridDim.x * blockDim.x;
    for (; i < n8; i += stride) {
        float4 a = in[2 * i], b = in[2 * i + 1];
        __half2 h0 = __floats2half2_rn(a.x, a.y);
        __half2 h1 = __floats2half2_rn(a.z, a.w);
        __half2 h2 = __floats2half2_rn(b.x, b.y);
        __half2 h3 = __floats2half2_rn(b.z, b.w);
        out[i] = make_uint4(*(uint32_t*)&h0, *(uint32_t*)&h1,
                            *(uint32_t*)&h2, *(uint32_t*)&h3);
    }
}

// ---------------- embedding ----------------
__global__ void embed_kernel(const int* __restrict__ ctx, const float* __restrict__ tok,
                             const float* __restrict__ pos, float* __restrict__ x)
{
    int row = blockIdx.x;
    int t   = row % TT;
    int token = ctx[row];
    int tid = threadIdx.x;
    float4 te = ((const float4*)(tok + (size_t)token * EE))[tid];
    float4 pe = ((const float4*)(pos + (size_t)t * EE))[tid];
    ((float4*)(x + (size_t)row * EE))[tid] =
        make_float4(te.x + pe.x, te.y + pe.y, te.z + pe.z, te.w + pe.w);
}

// ---------------- layernorm: WARP per row ----------------
__global__ void ln_kernel(const float* __restrict__ x, const float* __restrict__ g,
                          const float* __restrict__ b, __half* __restrict__ y)
{
    int warp = threadIdx.x >> 5, lane = threadIdx.x & 31;
    int row = blockIdx.x * 8 + warp;
    const float4* xr = (const float4*)(x + (size_t)row * EE);
    float4 xv[8];
    float s = 0.f, q = 0.f;
    #pragma unroll
    for (int i = 0; i < 8; i++) {
        xv[i] = xr[lane + 32 * i];
        s += xv[i].x + xv[i].y + xv[i].z + xv[i].w;
        q += xv[i].x * xv[i].x + xv[i].y * xv[i].y + xv[i].z * xv[i].z + xv[i].w * xv[i].w;
    }
    #pragma unroll
    for (int o = 16; o; o >>= 1) {
        s += __shfl_xor_sync(0xffffffffu, s, o);
        q += __shfl_xor_sync(0xffffffffu, q, o);
    }
    float mu  = s * (1.0f / EE);
    float var = fmaxf(q * (1.0f / EE) - mu * mu, 0.f);
    float rs  = rsqrtf(var + 1e-5f);
    __half* yr = y + (size_t)row * EE;
    #pragma unroll
    for (int i = 0; i < 8; i++) {
        float4 gv = ((const float4*)g)[lane + 32 * i];
        float4 bv = ((const float4*)b)[lane + 32 * i];
        __half2 h0 = __floats2half2_rn((xv[i].x - mu) * rs * gv.x + bv.x,
                                       (xv[i].y - mu) * rs * gv.y + bv.y);
        __half2 h1 = __floats2half2_rn((xv[i].z - mu) * rs * gv.z + bv.z,
                                       (xv[i].w - mu) * rs * gv.w + bv.w);
        *(uint2*)(yr + (lane + 32 * i) * 4) = make_uint2(*(uint32_t*)&h0, *(uint32_t*)&h1);
    }
}

// ---------------- fp16 GEMM, BM=128 (+ optional q-scale; + fused loss partials) ----
#define HSTR 40
#define ASZH (128*HSTR)
#define BSTRH 136
#define BSZH (32*BSTRH)
#define NSTG 4

__global__ __launch_bounds__(256, 2) void hgemm_kernel(
    const __half* __restrict__ A,
    const __half* __restrict__ w0, const __half* __restrict__ w1, const __half* __restrict__ w2,
    int wN,
    const float* __restrict__ bias, const float* __restrict__ res,
    void* c0, void* c1, void* c2,
    int K, int relu, int outHalf, int scaleq, int lossmode)
{
    extern __shared__ __half sm[];
    __half* As = sm;
    __half* Bs = sm + NSTG * ASZH;

    int tid = threadIdx.x;
    int warp = tid >> 5, lane = tid & 31;
    int g = lane >> 2, t = lane & 3;
    int lrow = lane & 15, lk = (lane >> 4) * 8;
    int wm = (warp & 3) * 32;
    int wn = (warp >> 2) * 64;
    int row0 = blockIdx.x * 128;
    int col0 = blockIdx.y * 128;

    int chunk = col0 / wN;
    int lcol0 = col0 - chunk * wN;
    const __half* W = (chunk == 0) ? w0 : (chunk == 1 ? w1 : w2);
    void* C = (chunk == 0) ? c0 : (chunk == 1 ? c1 : c2);
    const __half* Ab = A + (size_t)row0 * K;
    const __half* Wb = W + lcol0;
    float osc = (scaleq && chunk == 0) ? 0.03125f : 1.0f;

    float acc[2][8][4] = {};

    auto issue = [&](int st, int k0) {
        __half* as = As + st * ASZH;
        __half* bs = Bs + st * BSZH;
        #pragma unroll
        for (int i = 0; i < 2; i++) {
            int idx = tid + i * 256;
            int m = idx >> 2, kq = (idx & 3) * 8;
            cp16h(&as[m * HSTR + kq], Ab + (size_t)m * K + k0 + kq);
            int kr = idx >> 4, nq = (idx & 15) * 8;
            cp16h(&bs[kr * BSTRH + nq], Wb + (size_t)(k0 + kr) * wN + nq);
        }
    };
    auto compute = [&](int st) {
        uint32_t asb = smem_u32(As + st * ASZH);
        uint32_t bsb = smem_u32(Bs + st * BSZH);
        #pragma unroll
        for (int kk = 0; kk < 2; kk++) {
            int kb = kk * 16;
            uint32_t af[2][4], bf[8][2];
            #pragma unroll
            for (int mi = 0; mi < 2; mi++)
                ldsm4(af[mi], asb + ((wm + mi * 16 + lrow) * HSTR + kb + lk) * 2);
            #pragma unroll
            for (int nj = 0; nj < 4; nj++) {
                uint32_t r[4];
                ldsm4t(r, bsb + ((kb + lrow) * BSTRH + wn + nj * 16 + lk) * 2);
                bf[2*nj][0]   = r[0]; bf[2*nj][1]   = r[1];
                bf[2*nj+1][0] = r[2]; bf[2*nj+1][1] = r[3];
            }
            #pragma unroll
            for (int mi = 0; mi < 2; mi++)
                #pragma unroll
                for (int ni = 0; ni < 8; ni++)
                    mma_f16(acc[mi][ni], af[mi], bf[ni]);
        }
    };

    int nks = K >> 5;
    issue(0, 0);  CP_COMMIT();
    issue(1, 32); CP_COMMIT();
    issue(2, 64); CP_COMMIT();
    for (int ks = 0; ks < nks; ks++) {
        int s = ks & (NSTG - 1);
        asm volatile("cp.async.wait_group 2;");
        __syncthreads();
        int kpf = ks + 3;
        if (kpf < nks) issue(kpf & (NSTG - 1), kpf * 32);
        CP_COMMIT();
        compute(s);
    }

    // ---- bias / res / relu / scale applied in-place ----
    #pragma unroll
    for (int mi = 0; mi < 2; mi++) {
        int r = row0 + wm + mi * 16 + g;
        #pragma unroll
        for (int ni = 0; ni < 8; ni++) {
            int c = lcol0 + wn + ni * 8 + t * 2;
            float* a = acc[mi][ni];
            if (bias) { float b0 = bias[c], b1 = bias[c + 1]; a[0] += b0; a[1] += b1; a[2] += b0; a[3] += b1; }
            if (res) {
                a[0] += res[(size_t)r * wN + c];       a[1] += res[(size_t)r * wN + c + 1];
                a[2] += res[(size_t)(r + 8) * wN + c]; a[3] += res[(size_t)(r + 8) * wN + c + 1];
            }
            if (relu) { a[0] = fmaxf(a[0], 0.f); a[1] = fmaxf(a[1], 0.f); a[2] = fmaxf(a[2], 0.f); a[3] = fmaxf(a[3], 0.f); }
            if (scaleq) { a[0] *= osc; a[1] *= osc; a[2] *= osc; a[3] *= osc; }
            if (outHalf) {
                __half* Ch = (__half*)C;
                *(__half2*)&Ch[(size_t)r * wN + c]       = __floats2half2_rn(a[0], a[1]);
                *(__half2*)&Ch[(size_t)(r + 8) * wN + c] = __floats2half2_rn(a[2], a[3]);
            } else {
                float* Cf = (float*)C;
                *(float2*)&Cf[(size_t)r * wN + c]       = make_float2(a[0], a[1]);
                *(float2*)&Cf[(size_t)(r + 8) * wN + c] = make_float2(a[2], a[3]);
            }
        }
    }

    // ---- fused loss partials: per (row, 64-col segment) online (max, sumexp) ----
    if (lossmode) {
        int seg = (lcol0 + wn) >> 6;
        #pragma unroll
        for (int mi = 0; mi < 2; mi++) {
            #pragma unroll
            for (int half = 0; half < 2; half++) {
                int r = row0 + wm + mi * 16 + g + half * 8;
                float m = -1e30f;
                #pragma unroll
                for (int ni = 0; ni < 8; ni++)
                    m = fmaxf(m, fmaxf(acc[mi][ni][half*2], acc[mi][ni][half*2+1]));
                m = fmaxf(m, __shfl_xor_sync(0xffffffffu, m, 1));
                m = fmaxf(m, __shfl_xor_sync(0xffffffffu, m, 2));
                float s = 0.f;
                #pragma unroll
                for (int ni = 0; ni < 8; ni++)
                    s += mexp(acc[mi][ni][half*2] - m) + mexp(acc[mi][ni][half*2+1] - m);
                s += __shfl_xor_sync(0xffffffffu, s, 1);
                s += __shfl_xor_sync(0xffffffffu, s, 2);
                if (t == 0)
                    g_lpart[(size_t)r * NSEG + seg] = make_float2(m, s);
            }
        }
    }
}

// ---------------- flash attention: P in registers, single sync/tile ----------------
#define FSTR 72
#define FTSZ (64*FSTR)
__global__ __launch_bounds__(128, 3) void flash_kernel(
    const __half* __restrict__ q, const __half* __restrict__ k,
    const __half* __restrict__ v, __half* __restrict__ o)
{
    extern __shared__ __half fsm[];
    __half* Qs = fsm;
    __half* Ks = fsm + FTSZ;
    __half* Vs = fsm + 3 * FTSZ;

    int bh = blockIdx.x;
    int qt = (int)gridDim.y - 1 - (int)blockIdx.y;
    int b = bh >> 4, h = bh & 15;
    int q0 = qt * 64;

    int tid = threadIdx.x;
    int warp = tid >> 5, lane = tid & 31;
    int g = lane >> 2, t = lane & 3;
    int lrow = lane & 15, lk = (lane >> 4) * 8;
    int wq = warp * 16;
    int r0 = wq + g;

    uint32_t qsb = smem_u32(Qs);

    auto issueKV = [&](int buf, int k0) {
        __half* Kd = Ks + buf * FTSZ;
        __half* Vd = Vs + buf * FTSZ;
        #pragma unroll
        for (int i = 0; i < 4; i++) {
            int idx = tid + i * 128;
            int r = idx >> 3, dq = (idx & 7) * 8;
            cp16h(&Kd[r * FSTR + dq], k + (size_t)(b * TT + k0 + r) * EE + h * 64 + dq);
            cp16h(&Vd[r * FSTR + dq], v + (size_t)(b * TT + k0 + r) * EE + h * 64 + dq);
        }
    };

    #pragma unroll
    for (int i = 0; i < 4; i++) {
        int idx = tid + i * 128;
        int r = idx >> 3, dq = (idx & 7) * 8;
        *(uint4*)&Qs[r * FSTR + dq] =
            *(const uint4*)(q + (size_t)(b * TT + q0 + r) * EE + h * 64 + dq);
    }
    issueKV(0, 0);
    CP_COMMIT();

    float accO[8][4] = {};
    float mr0 = -1e30f, mr1 = -1e30f, lr0 = 0.f, lr1 = 0.f;

    for (int kt = 0; kt <= qt; kt++) {
        int buf = kt & 1;
        asm volatile("cp.async.wait_group 0;");
        __syncthreads();
        if (kt < qt) {
            issueKV(buf ^ 1, (kt + 1) * 64);
            CP_COMMIT();
        }

        uint32_t ksb = smem_u32(Ks + buf * FTSZ);
        uint32_t vsb = smem_u32(Vs + buf * FTSZ);

        float accS[8][4] = {};
        #pragma unroll
        for (int kb = 0; kb < 64; kb += 16) {
            uint32_t af[4];
            ldsm4(af, qsb + ((wq + lrow) * FSTR + kb + lk) * 2);
            #pragma unroll
            for (int nj = 0; nj < 4; nj++) {
                uint32_t r[4];
                ldsm4(r, ksb + ((nj * 16 + lrow) * FSTR + kb + lk) * 2);
                uint32_t bf0[2] = { r[0], r[2] };
                uint32_t bf1[2] = { r[1], r[3] };
                mma_f16(accS[2*nj],   af, bf0);
                mma_f16(accS[2*nj+1], af, bf1);
            }
        }

        bool diag = (kt == qt);
        if (diag) {
            #pragma unroll
            for (int ni = 0; ni < 8; ni++) {
                int c = ni * 8 + t * 2;
                if (c     > r0)     accS[ni][0] = -1e30f;
                if (c + 1 > r0)     accS[ni][1] = -1e30f;
                if (c     > r0 + 8) accS[ni][2] = -1e30f;
                if (c + 1 > r0 + 8) accS[ni][3] = -1e30f;
            }
        }

        float m0 = -1e30f, m1 = -1e30f;
        #pragma unroll
        for (int ni = 0; ni < 8; ni++) {
            m0 = fmaxf(m0, fmaxf(accS[ni][0], accS[ni][1]));
            m1 = fmaxf(m1, fmaxf(accS[ni][2], accS[ni][3]));
        }
        m0 = fmaxf(m0, __shfl_xor_sync(0xffffffffu, m0, 1));
        m0 = fmaxf(m0, __shfl_xor_sync(0xffffffffu, m0, 2));
        m1 = fmaxf(m1, __shfl_xor_sync(0xffffffffu, m1, 1));
        m1 = fmaxf(m1, __shfl_xor_sync(0xffffffffu, m1, 2));

        float mn0 = fmaxf(mr0, m0), mn1 = fmaxf(mr1, m1);
        float a0 = mexp(mr0 - mn0), a1 = mexp(mr1 - mn1);

        float s0 = 0.f, s1 = 0.f;
        #pragma unroll
        for (int ni = 0; ni < 8; ni++) {
            accS[ni][0] = mexp(accS[ni][0] - mn0);
            accS[ni][1] = mexp(accS[ni][1] - mn0);
            accS[ni][2] = mexp(accS[ni][2] - mn1);
            accS[ni][3] = mexp(accS[ni][3] - mn1);
            s0 += accS[ni][0] + accS[ni][1];
            s1 += accS[ni][2] + accS[ni][3];
        }
        s0 += __shfl_xor_sync(0xffffffffu, s0, 1);
        s0 += __shfl_xor_sync(0xffffffffu, s0, 2);
        s1 += __shfl_xor_sync(0xffffffffu, s1, 1);
        s1 += __shfl_xor_sync(0xffffffffu, s1, 2);

        lr0 = lr0 * a0 + s0;
        lr1 = lr1 * a1 + s1;
        mr0 = mn0; mr1 = mn1;

        #pragma unroll
        for (int ni = 0; ni < 8; ni++) {
            accO[ni][0] *= a0; accO[ni][1] *= a0;
            accO[ni][2] *= a1; accO[ni][3] *= a1;
        }

        #pragma unroll
        for (int j = 0; j < 4; j++) {
            uint32_t af[4];
            af[0] = h2pack(accS[2*j][0],   accS[2*j][1]);
            af[1] = h2pack(accS[2*j][2],   accS[2*j][3]);
            af[2] = h2pack(accS[2*j+1][0], accS[2*j+1][1]);
            af[3] = h2pack(accS[2*j+1][2], accS[2*j+1][3]);
            int kb = j * 16;
            #pragma unroll
            for (int nj = 0; nj < 4; nj++) {
                uint32_t r[4];
                ldsm4t(r, vsb + ((kb + lrow) * FSTR + nj * 16 + lk) * 2);
                uint32_t bf0[2] = { r[0], r[1] };
                uint32_t bf1[2] = { r[2], r[3] };
                mma_f16(accO[2*nj],   af, bf0);
                mma_f16(accO[2*nj+1], af, bf1);
            }
        }
    }

    float i0 = 1.f / lr0, i1 = 1.f / lr1;
    #pragma unroll
    for (int ni = 0; ni < 8; ni++) {
        int d = ni * 8 + 2 * t;
        *(__half2*)(o + (size_t)(b * TT + q0 + r0) * EE + h * 64 + d) =
            __floats2half2_rn(accO[ni][0] * i0, accO[ni][1] * i0);
        *(__half2*)(o + (size_t)(b * TT + q0 + r0 + 8) * EE + h * 64 + d) =
            __floats2half2_rn(accO[ni][2] * i1, accO[ni][3] * i1);
    }
}

// ---------------- loss: merge per-segment partials ----------------
__global__ void loss_merge_kernel(const float2* __restrict__ part,
                                  const float* __restrict__ logits,
                                  const int* __restrict__ targets,
                                  float* __restrict__ rowloss)
{
    int row = blockIdx.x, tid = threadIdx.x;  // 128 threads
    const float2* pr = part + (size_t)row * NSEG;
    float m = -1e30f, s = 0.f;
    for (int i = tid; i < NSEG; i += 128) {
        float2 p = pr[i];
        float M = fmaxf(m, p.x);
        s = s * mexp(m - M) + p.y * mexp(p.x - M);
        m = M;
    }
    #pragma unroll
    for (int o = 16; o; o >>= 1) {
        float m2 = __shfl_xor_sync(0xffffffffu, m, o);
        float s2 = __shfl_xor_sync(0xffffffffu, s, o);
        float M = fmaxf(m, m2);
        s = s * mexp(m - M) + s2 * mexp(m2 - M);
        m = M;
    }
    __shared__ float sm_[4], ss_[4];
    int w = tid >> 5;
    if ((tid & 31) == 0) { sm_[w] = m; ss_[w] = s; }
    __syncthreads();
    if (tid == 0) {
        m = sm_[0]; s = ss_[0];
        for (int i = 1; i < 4; i++) {
            float M = fmaxf(m, sm_[i]);
            s = s * mexp(m - M) + ss_[i] * mexp(sm_[i] - M);
            m = M;
        }
        float lse = m + logf(s);
        rowloss[row] = lse - logits[(size_t)row * VV + targets[row]];
    }
}

__global__ void loss_reduce_kernel(const float* __restrict__ rowloss, float* __restrict__ out)
{
    __shared__ float red[256];
    int tid = threadIdx.x;
    float s = 0.f;
    for (int i = tid; i < MROWS; i += 256) s += rowloss[i];
    red[tid] = s; __syncthreads();
    for (int o = 128; o > 0; o >>= 1) { if (tid < o) red[tid] += red[tid + o]; __syncthreads(); }
    if (tid == 0) out[0] = red[0] * (1.0f / MROWS);
}

// ---------------- host orchestration ----------------
#define SMEMG (NSTG * (ASZH + BSZH) * 2)   // 75776
#define SMEMF (5 * FTSZ * 2)               // 46080

extern "C" void kernel_launch(void* const* d_in, const int* in_sizes, int n_in,
                              void* d_out, int out_size)
{
    const int*   ctx  = (const int*)  d_in[0];
    const int*   tgt  = (const int*)  d_in[1];
    const float* tok  = (const float*)d_in[2];
    const float* pos  = (const float*)d_in[3];
    const float* Wq   = (const float*)d_in[4];
    const float* Wk   = (const float*)d_in[5];
    const float* Wv   = (const float*)d_in[6];
    const float* Wo   = (const float*)d_in[7];
    const float* bo   = (const float*)d_in[8];
    const float* ln1g = (const float*)d_in[9];
    const float* ln1b = (const float*)d_in[10];
    const float* ln2g = (const float*)d_in[11];
    const float* ln2b = (const float*)d_in[12];
    const float* W1   = (const float*)d_in[13];
    const float* b1   = (const float*)d_in[14];
    const float* W2   = (const float*)d_in[15];
    const float* b2   = (const float*)d_in[16];
    const float* lnfg = (const float*)d_in[17];
    const float* lnfb = (const float*)d_in[18];
    const float* Wlm  = (const float*)d_in[19];
    const float* blm  = (const float*)d_in[20];

    static float *px = nullptr, *prl;
    static float2 *plp;
    static __half *ph, *pq, *pk, *pv, *po, *pff;
    static __half *whq, *whk, *whv, *who, *wh1, *wh2, *whlm;
    static cudaStream_t s2;
    static cudaEvent_t evFork, evQ[LL], evW[LL], evLM;
    if (!px) {
        cudaGetSymbolAddress((void**)&px,  g_x);
        cudaGetSymbolAddress((void**)&prl, g_rowloss);
        cudaGetSymbolAddress((void**)&plp, g_lpart);
        cudaGetSymbolAddress((void**)&ph,  g_h);
        cudaGetSymbolAddress((void**)&pq,  g_q);
        cudaGetSymbolAddress((void**)&pk,  g_k);
        cudaGetSymbolAddress((void**)&pv,  g_v);
        cudaGetSymbolAddress((void**)&po,  g_o);
        cudaGetSymbolAddress((void**)&pff, g_ff);
        cudaGetSymbolAddress((void**)&whq, g_whq);
        cudaGetSymbolAddress((void**)&whk, g_whk);
        cudaGetSymbolAddress((void**)&whv, g_whv);
        cudaGetSymbolAddress((void**)&who, g_who);
        cudaGetSymbolAddress((void**)&wh1, g_wh1);
        cudaGetSymbolAddress((void**)&wh2, g_wh2);
        cudaGetSymbolAddress((void**)&whlm, g_whlm);
        cudaFuncSetAttribute(hgemm_kernel, cudaFuncAttributeMaxDynamicSharedMemorySize, SMEMG);
        cudaFuncSetAttribute(flash_kernel, cudaFuncAttributeMaxDynamicSharedMemorySize, SMEMF);
        int loPr, hiPr;
        cudaDeviceGetStreamPriorityRange(&loPr, &hiPr);
        cudaStreamCreateWithPriority(&s2, cudaStreamNonBlocking, loPr);
        cudaEventCreateWithFlags(&evFork, cudaEventDisableTiming);
        for (int l = 0; l < LL; l++) {
            cudaEventCreateWithFlags(&evQ[l], cudaEventDisableTiming);
            cudaEventCreateWithFlags(&evW[l], cudaEventDisableTiming);
        }
        cudaEventCreateWithFlags(&evLM, cudaEventDisableTiming);
    }
    float* out = (float*)d_out;

    // ---- fork low-priority side stream; convert weights per-layer, QKV first ----
    cudaEventRecord(evFork, 0);
    cudaStreamWaitEvent(s2, evFork, 0);
    const int EEE8 = EE * EE / 8, EFF8 = EE * FF_ / 8;
    for (int l = 0; l < LL; l++) {
        size_t oE = (size_t)l * EE * EE, oF = (size_t)l * EE * FF_;
        conv_h2<<<512,  256, 0, s2>>>((const float4*)(Wq + oE), (uint4*)(whq + oE), EEE8);
        conv_h2<<<512,  256, 0, s2>>>((const float4*)(Wk + oE), (uint4*)(whk + oE), EEE8);
        conv_h2<<<512,  256, 0, s2>>>((const float4*)(Wv + oE), (uint4*)(whv + oE), EEE8);
        cudaEventRecord(evQ[l], s2);
        conv_h2<<<512,  256, 0, s2>>>((const float4*)(Wo + oE), (uint4*)(who + oE), EEE8);
        conv_h2<<<2048, 256, 0, s2>>>((const float4*)(W1 + oF), (uint4*)(wh1 + oF), EFF8);
        conv_h2<<<2048, 256, 0, s2>>>((const float4*)(W2 + oF), (uint4*)(wh2 + oF), EFF8);
        cudaEventRecord(evW[l], s2);
    }
    conv_h2<<<8192, 256, 0, s2>>>((const float4*)Wlm, (uint4*)whlm, EE * VV / 8);
    cudaEventRecord(evLM, s2);

    embed_kernel<<<MROWS, 256>>>(ctx, tok, pos, px);

    dim3 gQKV(16, 24);
    dim3 gEo (16, 8);
    dim3 gF1 (16, 32);
    dim3 gLM (16, 250);
    dim3 gFA (32, 16);
    int gLN = MROWS / 8;

    for (int l = 0; l < LL; l++) {
        size_t oE = (size_t)l * EE * EE, oF = (size_t)l * EE * FF_;

        ln_kernel<<<gLN, 256>>>(px, ln1g + l * EE, ln1b + l * EE, ph);

        cudaStreamWaitEvent(0, evQ[l], 0);
        hgemm_kernel<<<gQKV, 256, SMEMG>>>(ph, whq + oE, whk + oE, whv + oE, EE,
                                           nullptr, nullptr, pq, pk, pv, EE, 0, 1, 1, 0);

        flash_kernel<<<gFA, 128, SMEMF>>>(pq, pk, pv, po);

        cudaStreamWaitEvent(0, evW[l], 0);
        hgemm_kernel<<<gEo, 256, SMEMG>>>(po, who + oE, who + oE, who + oE, EE,
                                          bo + l * EE, px, px, px, px, EE, 0, 0, 0, 0);

        ln_kernel<<<gLN, 256>>>(px, ln2g + l * EE, ln2b + l * EE, ph);

        hgemm_kernel<<<gF1, 256, SMEMG>>>(ph, wh1 + oF, wh1 + oF, wh1 + oF, FF_,
                                          b1 + l * FF_, nullptr, pff, pff, pff, EE, 1, 1, 0, 0);

        hgemm_kernel<<<gEo, 256, SMEMG>>>(pff, wh2 + oF, wh2 + oF, wh2 + oF, EE,
                                          b2 + l * EE, px, px, px, px, FF_, 0, 0, 0, 0);
    }

    cudaStreamWaitEvent(0, evLM, 0);
    ln_kernel<<<gLN, 256>>>(px, lnfg, lnfb, ph);
    hgemm_kernel<<<gLM, 256, SMEMG>>>(ph, whlm, whlm, whlm, VV,
                                      blm, nullptr, out, out, out, EE, 0, 0, 0, 1);

    if (out_size > MROWS * VV) {
        loss_merge_kernel<<<MROWS, 128>>>(plp, out, tgt, prl);
        loss_reduce_kernel<<<1, 256>>>(prl, out + (size_t)MROWS * VV);
    }
}

// round 17
// speedup vs baseline: 1.0336x; 1.0336x over previous
#include <cuda_runtime.h>
#include <cuda_fp16.h>
#include <math.h>
#include <stdint.h>

#define BB   2
#define TT   1024
#define EE   1024
#define HH   16
#define HD   64
#define LL   8
#define FF_  4096
#define VV   32000
#define MROWS (BB*TT)          // 2048
#define NSEG (VV/64)           // 500

// ---------------- scratch ----------------
__device__ float  g_x  [MROWS*EE];
__device__ __half g_h  [MROWS*EE];
__device__ __half g_q  [MROWS*EE];
__device__ __half g_k  [MROWS*EE];
__device__ __half g_v  [MROWS*EE];
__device__ __half g_o  [MROWS*EE];
__device__ __half g_ff [MROWS*FF_];
__device__ float  g_rowloss[MROWS];
__device__ float2 g_lpart[(size_t)MROWS*NSEG];   // 8 MB loss partials
__device__ __half g_whq[LL*EE*EE];
__device__ __half g_whk[LL*EE*EE];
__device__ __half g_whv[LL*EE*EE];
__device__ __half g_who[LL*EE*EE];
__device__ __half g_wh1[LL*EE*FF_];
__device__ __half g_wh2[LL*FF_*EE];
__device__ __half g_whlm[(size_t)EE*VV];

// ---------------- helpers ----------------
__device__ __forceinline__ void mma_f16(float* d, const uint32_t* a, const uint32_t* b) {
    asm volatile(
        "mma.sync.aligned.m16n8k16.row.col.f32.f16.f16.f32 "
        "{%0,%1,%2,%3}, {%4,%5,%6,%7}, {%8,%9}, {%0,%1,%2,%3};"
        : "+f"(d[0]), "+f"(d[1]), "+f"(d[2]), "+f"(d[3])
        : "r"(a[0]), "r"(a[1]), "r"(a[2]), "r"(a[3]), "r"(b[0]), "r"(b[1]));
}
__device__ __forceinline__ void ldsm4(uint32_t* r, uint32_t addr) {
    asm volatile("ldmatrix.sync.aligned.m8n8.x4.shared.b16 {%0,%1,%2,%3}, [%4];"
        : "=r"(r[0]), "=r"(r[1]), "=r"(r[2]), "=r"(r[3]) : "r"(addr));
}
__device__ __forceinline__ void ldsm4t(uint32_t* r, uint32_t addr) {
    asm volatile("ldmatrix.sync.aligned.m8n8.x4.trans.shared.b16 {%0,%1,%2,%3}, [%4];"
        : "=r"(r[0]), "=r"(r[1]), "=r"(r[2]), "=r"(r[3]) : "r"(addr));
}
__device__ __forceinline__ uint32_t smem_u32(const void* p) {
    return (uint32_t)__cvta_generic_to_shared(p);
}
__device__ __forceinline__ void cp16h(__half* s, const __half* g) {
    uint32_t sa = smem_u32(s);
    asm volatile("cp.async.ca.shared.global [%0], [%1], 16;" :: "r"(sa), "l"(g));
}
#define CP_COMMIT() asm volatile("cp.async.commit_group;")

// MUFU-based exp
__device__ __forceinline__ float mexp(float x) {
    float r;
    asm("ex2.approx.f32 %0, %1;" : "=f"(r) : "f"(x * 1.44269504f));
    return r;
}
__device__ __forceinline__ uint32_t h2pack(float a, float b) {
    __half2 h = __floats2half2_rn(a, b);
    return *(uint32_t*)&h;
}

// ---------------- streaming fp32 -> fp16 convert ----------------
__global__ void conv_h2(const float4* __restrict__ in, uint4* __restrict__ out, int n8)
{
    int i = blockIdx.x * blockDim.x + threadIdx.x;
    int stride = gridDim.x * blockDim.x;
    for (; i < n8; i += stride) {
        float4 a = in[2 * i], b = in[2 * i + 1];
        __half2 h0 = __floats2half2_rn(a.x, a.y);
        __half2 h1 = __floats2half2_rn(a.z, a.w);
        __half2 h2 = __floats2half2_rn(b.x, b.y);
        __half2 h3 = __floats2half2_rn(b.z, b.w);
        out[i] = make_uint4(*(uint32_t*)&h0, *(uint32_t*)&h1,
                            *(uint32_t*)&h2, *(uint32_t*)&h3);
    }
}

// ---------------- embedding ----------------
__global__ void embed_kernel(const int* __restrict__ ctx, const float* __restrict__ tok,
                             const float* __restrict__ pos, float* __restrict__ x)
{
    int row = blockIdx.x;
    int t   = row % TT;
    int token = ctx[row];
    int tid = threadIdx.x;
    float4 te = ((const float4*)(tok + (size_t)token * EE))[tid];
    float4 pe = ((const float4*)(pos + (size_t)t * EE))[tid];
    ((float4*)(x + (size_t)row * EE))[tid] =
        make_float4(te.x + pe.x, te.y + pe.y, te.z + pe.z, te.w + pe.w);
}

// ---------------- layernorm: WARP per row ----------------
__global__ void ln_kernel(const float* __restrict__ x, const float* __restrict__ g,
                          const float* __restrict__ b, __half* __restrict__ y)
{
    int warp = threadIdx.x >> 5, lane = threadIdx.x & 31;
    int row = blockIdx.x * 8 + warp;
    const float4* xr = (const float4*)(x + (size_t)row * EE);
    float4 xv[8];
    float s = 0.f, q = 0.f;
    #pragma unroll
    for (int i = 0; i < 8; i++) {
        xv[i] = xr[lane + 32 * i];
        s += xv[i].x + xv[i].y + xv[i].z + xv[i].w;
        q += xv[i].x * xv[i].x + xv[i].y * xv[i].y + xv[i].z * xv[i].z + xv[i].w * xv[i].w;
    }
    #pragma unroll
    for (int o = 16; o; o >>= 1) {
        s += __shfl_xor_sync(0xffffffffu, s, o);
        q += __shfl_xor_sync(0xffffffffu, q, o);
    }
    float mu  = s * (1.0f / EE);
    float var = fmaxf(q * (1.0f / EE) - mu * mu, 0.f);
    float rs  = rsqrtf(var + 1e-5f);
    __half* yr = y + (size_t)row * EE;
    #pragma unroll
    for (int i = 0; i < 8; i++) {
        float4 gv = ((const float4*)g)[lane + 32 * i];
        float4 bv = ((const float4*)b)[lane + 32 * i];
        __half2 h0 = __floats2half2_rn((xv[i].x - mu) * rs * gv.x + bv.x,
                                       (xv[i].y - mu) * rs * gv.y + bv.y);
        __half2 h1 = __floats2half2_rn((xv[i].z - mu) * rs * gv.z + bv.z,
                                       (xv[i].w - mu) * rs * gv.w + bv.w);
        *(uint2*)(yr + (lane + 32 * i) * 4) = make_uint2(*(uint32_t*)&h0, *(uint32_t*)&h1);
    }
}

// ---------------- fp16 GEMM, BM=128 (EXACT round-15 version) ----------------
#define HSTR 40
#define ASZH (128*HSTR)
#define BSTRH 136
#define BSZH (32*BSTRH)
#define NSTG 4

__global__ __launch_bounds__(256, 2) void hgemm_kernel(
    const __half* __restrict__ A,
    const __half* __restrict__ w0, const __half* __restrict__ w1, const __half* __restrict__ w2,
    int wN,
    const float* __restrict__ bias, const float* __restrict__ res,
    void* c0, void* c1, void* c2,
    int K, int relu, int outHalf, int scaleq)
{
    extern __shared__ __half sm[];
    __half* As = sm;
    __half* Bs = sm + NSTG * ASZH;

    int tid = threadIdx.x;
    int warp = tid >> 5, lane = tid & 31;
    int g = lane >> 2, t = lane & 3;
    int lrow = lane & 15, lk = (lane >> 4) * 8;
    int wm = (warp & 3) * 32;
    int wn = (warp >> 2) * 64;
    int row0 = blockIdx.x * 128;
    int col0 = blockIdx.y * 128;

    int chunk = col0 / wN;
    int lcol0 = col0 - chunk * wN;
    const __half* W = (chunk == 0) ? w0 : (chunk == 1 ? w1 : w2);
    void* C = (chunk == 0) ? c0 : (chunk == 1 ? c1 : c2);
    const __half* Ab = A + (size_t)row0 * K;
    const __half* Wb = W + lcol0;
    float osc = (scaleq && chunk == 0) ? 0.03125f : 1.0f;

    float acc[2][8][4] = {};

    auto issue = [&](int st, int k0) {
        __half* as = As + st * ASZH;
        __half* bs = Bs + st * BSZH;
        #pragma unroll
        for (int i = 0; i < 2; i++) {
            int idx = tid + i * 256;
            int m = idx >> 2, kq = (idx & 3) * 8;
            cp16h(&as[m * HSTR + kq], Ab + (size_t)m * K + k0 + kq);
            int kr = idx >> 4, nq = (idx & 15) * 8;
            cp16h(&bs[kr * BSTRH + nq], Wb + (size_t)(k0 + kr) * wN + nq);
        }
    };
    auto compute = [&](int st) {
        uint32_t asb = smem_u32(As + st * ASZH);
        uint32_t bsb = smem_u32(Bs + st * BSZH);
        #pragma unroll
        for (int kk = 0; kk < 2; kk++) {
            int kb = kk * 16;
            uint32_t af[2][4], bf[8][2];
            #pragma unroll
            for (int mi = 0; mi < 2; mi++)
                ldsm4(af[mi], asb + ((wm + mi * 16 + lrow) * HSTR + kb + lk) * 2);
            #pragma unroll
            for (int nj = 0; nj < 4; nj++) {
                uint32_t r[4];
                ldsm4t(r, bsb + ((kb + lrow) * BSTRH + wn + nj * 16 + lk) * 2);
                bf[2*nj][0]   = r[0]; bf[2*nj][1]   = r[1];
                bf[2*nj+1][0] = r[2]; bf[2*nj+1][1] = r[3];
            }
            #pragma unroll
            for (int mi = 0; mi < 2; mi++)
                #pragma unroll
                for (int ni = 0; ni < 8; ni++)
                    mma_f16(acc[mi][ni], af[mi], bf[ni]);
        }
    };

    int nks = K >> 5;
    issue(0, 0);  CP_COMMIT();
    issue(1, 32); CP_COMMIT();
    issue(2, 64); CP_COMMIT();
    for (int ks = 0; ks < nks; ks++) {
        int s = ks & (NSTG - 1);
        asm volatile("cp.async.wait_group 2;");
        __syncthreads();
        int kpf = ks + 3;
        if (kpf < nks) issue(kpf & (NSTG - 1), kpf * 32);
        CP_COMMIT();
        compute(s);
    }

    #pragma unroll
    for (int mi = 0; mi < 2; mi++) {
        int r = row0 + wm + mi * 16 + g;
        #pragma unroll
        for (int ni = 0; ni < 8; ni++) {
            int c = lcol0 + wn + ni * 8 + t * 2;
            float v0 = acc[mi][ni][0], v1 = acc[mi][ni][1];
            float v2 = acc[mi][ni][2], v3 = acc[mi][ni][3];
            if (bias) { float b0 = bias[c], b1 = bias[c + 1]; v0 += b0; v1 += b1; v2 += b0; v3 += b1; }
            if (res) {
                v0 += res[(size_t)r * wN + c];       v1 += res[(size_t)r * wN + c + 1];
                v2 += res[(size_t)(r + 8) * wN + c]; v3 += res[(size_t)(r + 8) * wN + c + 1];
            }
            if (relu) { v0 = fmaxf(v0, 0.f); v1 = fmaxf(v1, 0.f); v2 = fmaxf(v2, 0.f); v3 = fmaxf(v3, 0.f); }
            v0 *= osc; v1 *= osc; v2 *= osc; v3 *= osc;
            if (outHalf) {
                __half* Ch = (__half*)C;
                *(__half2*)&Ch[(size_t)r * wN + c]       = __floats2half2_rn(v0, v1);
                *(__half2*)&Ch[(size_t)(r + 8) * wN + c] = __floats2half2_rn(v2, v3);
            } else {
                float* Cf = (float*)C;
                *(float2*)&Cf[(size_t)r * wN + c]       = make_float2(v0, v1);
                *(float2*)&Cf[(size_t)(r + 8) * wN + c] = make_float2(v2, v3);
            }
        }
    }
}

// ---------------- LM-head GEMM clone: bias + fp32 out + fused loss partials --------
__global__ __launch_bounds__(256, 2) void hgemm_lm_kernel(
    const __half* __restrict__ A, const __half* __restrict__ W,
    const float* __restrict__ bias, float* __restrict__ C, int K)
{
    const int wN = VV;
    extern __shared__ __half sm[];
    __half* As = sm;
    __half* Bs = sm + NSTG * ASZH;

    int tid = threadIdx.x;
    int warp = tid >> 5, lane = tid & 31;
    int g = lane >> 2, t = lane & 3;
    int lrow = lane & 15, lk = (lane >> 4) * 8;
    int wm = (warp & 3) * 32;
    int wn = (warp >> 2) * 64;
    int row0 = blockIdx.x * 128;
    int col0 = blockIdx.y * 128;

    const __half* Ab = A + (size_t)row0 * K;
    const __half* Wb = W + col0;

    float acc[2][8][4] = {};

    auto issue = [&](int st, int k0) {
        __half* as = As + st * ASZH;
        __half* bs = Bs + st * BSZH;
        #pragma unroll
        for (int i = 0; i < 2; i++) {
            int idx = tid + i * 256;
            int m = idx >> 2, kq = (idx & 3) * 8;
            cp16h(&as[m * HSTR + kq], Ab + (size_t)m * K + k0 + kq);
            int kr = idx >> 4, nq = (idx & 15) * 8;
            cp16h(&bs[kr * BSTRH + nq], Wb + (size_t)(k0 + kr) * wN + nq);
        }
    };
    auto compute = [&](int st) {
        uint32_t asb = smem_u32(As + st * ASZH);
        uint32_t bsb = smem_u32(Bs + st * BSZH);
        #pragma unroll
        for (int kk = 0; kk < 2; kk++) {
            int kb = kk * 16;
            uint32_t af[2][4], bf[8][2];
            #pragma unroll
            for (int mi = 0; mi < 2; mi++)
                ldsm4(af[mi], asb + ((wm + mi * 16 + lrow) * HSTR + kb + lk) * 2);
            #pragma unroll
            for (int nj = 0; nj < 4; nj++) {
                uint32_t r[4];
                ldsm4t(r, bsb + ((kb + lrow) * BSTRH + wn + nj * 16 + lk) * 2);
                bf[2*nj][0]   = r[0]; bf[2*nj][1]   = r[1];
                bf[2*nj+1][0] = r[2]; bf[2*nj+1][1] = r[3];
            }
            #pragma unroll
            for (int mi = 0; mi < 2; mi++)
                #pragma unroll
                for (int ni = 0; ni < 8; ni++)
                    mma_f16(acc[mi][ni], af[mi], bf[ni]);
        }
    };

    int nks = K >> 5;
    issue(0, 0);  CP_COMMIT();
    issue(1, 32); CP_COMMIT();
    issue(2, 64); CP_COMMIT();
    for (int ks = 0; ks < nks; ks++) {
        int s = ks & (NSTG - 1);
        asm volatile("cp.async.wait_group 2;");
        __syncthreads();
        int kpf = ks + 3;
        if (kpf < nks) issue(kpf & (NSTG - 1), kpf * 32);
        CP_COMMIT();
        compute(s);
    }

    // epilogue: bias in-place, store fp32, fused per-segment loss partials
    #pragma unroll
    for (int mi = 0; mi < 2; mi++) {
        int r = row0 + wm + mi * 16 + g;
        #pragma unroll
        for (int ni = 0; ni < 8; ni++) {
            int c = col0 + wn + ni * 8 + t * 2;
            float* a = acc[mi][ni];
            float b0 = bias[c], b1 = bias[c + 1];
            a[0] += b0; a[1] += b1; a[2] += b0; a[3] += b1;
            *(float2*)&C[(size_t)r * wN + c]       = make_float2(a[0], a[1]);
            *(float2*)&C[(size_t)(r + 8) * wN + c] = make_float2(a[2], a[3]);
        }
    }
    int seg = (col0 + wn) >> 6;
    #pragma unroll
    for (int mi = 0; mi < 2; mi++) {
        #pragma unroll
        for (int half = 0; half < 2; half++) {
            int r = row0 + wm + mi * 16 + g + half * 8;
            float m = -1e30f;
            #pragma unroll
            for (int ni = 0; ni < 8; ni++)
                m = fmaxf(m, fmaxf(acc[mi][ni][half*2], acc[mi][ni][half*2+1]));
            m = fmaxf(m, __shfl_xor_sync(0xffffffffu, m, 1));
            m = fmaxf(m, __shfl_xor_sync(0xffffffffu, m, 2));
            float s = 0.f;
            #pragma unroll
            for (int ni = 0; ni < 8; ni++)
                s += mexp(acc[mi][ni][half*2] - m) + mexp(acc[mi][ni][half*2+1] - m);
            s += __shfl_xor_sync(0xffffffffu, s, 1);
            s += __shfl_xor_sync(0xffffffffu, s, 2);
            if (t == 0)
                g_lpart[(size_t)r * NSEG + seg] = make_float2(m, s);
        }
    }
}

// ---------------- flash attention: P in registers, single sync/tile ----------------
#define FSTR 72
#define FTSZ (64*FSTR)
__global__ __launch_bounds__(128, 3) void flash_kernel(
    const __half* __restrict__ q, const __half* __restrict__ k,
    const __half* __restrict__ v, __half* __restrict__ o)
{
    extern __shared__ __half fsm[];
    __half* Qs = fsm;
    __half* Ks = fsm + FTSZ;
    __half* Vs = fsm + 3 * FTSZ;

    int bh = blockIdx.x;
    int qt = (int)gridDim.y - 1 - (int)blockIdx.y;
    int b = bh >> 4, h = bh & 15;
    int q0 = qt * 64;

    int tid = threadIdx.x;
    int warp = tid >> 5, lane = tid & 31;
    int g = lane >> 2, t = lane & 3;
    int lrow = lane & 15, lk = (lane >> 4) * 8;
    int wq = warp * 16;
    int r0 = wq + g;

    uint32_t qsb = smem_u32(Qs);

    auto issueKV = [&](int buf, int k0) {
        __half* Kd = Ks + buf * FTSZ;
        __half* Vd = Vs + buf * FTSZ;
        #pragma unroll
        for (int i = 0; i < 4; i++) {
            int idx = tid + i * 128;
            int r = idx >> 3, dq = (idx & 7) * 8;
            cp16h(&Kd[r * FSTR + dq], k + (size_t)(b * TT + k0 + r) * EE + h * 64 + dq);
            cp16h(&Vd[r * FSTR + dq], v + (size_t)(b * TT + k0 + r) * EE + h * 64 + dq);
        }
    };

    #pragma unroll
    for (int i = 0; i < 4; i++) {
        int idx = tid + i * 128;
        int r = idx >> 3, dq = (idx & 7) * 8;
        *(uint4*)&Qs[r * FSTR + dq] =
            *(const uint4*)(q + (size_t)(b * TT + q0 + r) * EE + h * 64 + dq);
    }
    issueKV(0, 0);
    CP_COMMIT();

    float accO[8][4] = {};
    float mr0 = -1e30f, mr1 = -1e30f, lr0 = 0.f, lr1 = 0.f;

    for (int kt = 0; kt <= qt; kt++) {
        int buf = kt & 1;
        asm volatile("cp.async.wait_group 0;");
        __syncthreads();
        if (kt < qt) {
            issueKV(buf ^ 1, (kt + 1) * 64);
            CP_COMMIT();
        }

        uint32_t ksb = smem_u32(Ks + buf * FTSZ);
        uint32_t vsb = smem_u32(Vs + buf * FTSZ);

        float accS[8][4] = {};
        #pragma unroll
        for (int kb = 0; kb < 64; kb += 16) {
            uint32_t af[4];
            ldsm4(af, qsb + ((wq + lrow) * FSTR + kb + lk) * 2);
            #pragma unroll
            for (int nj = 0; nj < 4; nj++) {
                uint32_t r[4];
                ldsm4(r, ksb + ((nj * 16 + lrow) * FSTR + kb + lk) * 2);
                uint32_t bf0[2] = { r[0], r[2] };
                uint32_t bf1[2] = { r[1], r[3] };
                mma_f16(accS[2*nj],   af, bf0);
                mma_f16(accS[2*nj+1], af, bf1);
            }
        }

        bool diag = (kt == qt);
        if (diag) {
            #pragma unroll
            for (int ni = 0; ni < 8; ni++) {
                int c = ni * 8 + t * 2;
                if (c     > r0)     accS[ni][0] = -1e30f;
                if (c + 1 > r0)     accS[ni][1] = -1e30f;
                if (c     > r0 + 8) accS[ni][2] = -1e30f;
                if (c + 1 > r0 + 8) accS[ni][3] = -1e30f;
            }
        }

        float m0 = -1e30f, m1 = -1e30f;
        #pragma unroll
        for (int ni = 0; ni < 8; ni++) {
            m0 = fmaxf(m0, fmaxf(accS[ni][0], accS[ni][1]));
            m1 = fmaxf(m1, fmaxf(accS[ni][2], accS[ni][3]));
        }
        m0 = fmaxf(m0, __shfl_xor_sync(0xffffffffu, m0, 1));
        m0 = fmaxf(m0, __shfl_xor_sync(0xffffffffu, m0, 2));
        m1 = fmaxf(m1, __shfl_xor_sync(0xffffffffu, m1, 1));
        m1 = fmaxf(m1, __shfl_xor_sync(0xffffffffu, m1, 2));

        float mn0 = fmaxf(mr0, m0), mn1 = fmaxf(mr1, m1);
        float a0 = mexp(mr0 - mn0), a1 = mexp(mr1 - mn1);

        float s0 = 0.f, s1 = 0.f;
        #pragma unroll
        for (int ni = 0; ni < 8; ni++) {
            accS[ni][0] = mexp(accS[ni][0] - mn0);
            accS[ni][1] = mexp(accS[ni][1] - mn0);
            accS[ni][2] = mexp(accS[ni][2] - mn1);
            accS[ni][3] = mexp(accS[ni][3] - mn1);
            s0 += accS[ni][0] + accS[ni][1];
            s1 += accS[ni][2] + accS[ni][3];
        }
        s0 += __shfl_xor_sync(0xffffffffu, s0, 1);
        s0 += __shfl_xor_sync(0xffffffffu, s0, 2);
        s1 += __shfl_xor_sync(0xffffffffu, s1, 1);
        s1 += __shfl_xor_sync(0xffffffffu, s1, 2);

        lr0 = lr0 * a0 + s0;
        lr1 = lr1 * a1 + s1;
        mr0 = mn0; mr1 = mn1;

        #pragma unroll
        for (int ni = 0; ni < 8; ni++) {
            accO[ni][0] *= a0; accO[ni][1] *= a0;
            accO[ni][2] *= a1; accO[ni][3] *= a1;
        }

        #pragma unroll
        for (int j = 0; j < 4; j++) {
            uint32_t af[4];
            af[0] = h2pack(accS[2*j][0],   accS[2*j][1]);
            af[1] = h2pack(accS[2*j][2],   accS[2*j][3]);
            af[2] = h2pack(accS[2*j+1][0], accS[2*j+1][1]);
            af[3] = h2pack(accS[2*j+1][2], accS[2*j+1][3]);
            int kb = j * 16;
            #pragma unroll
            for (int nj = 0; nj < 4; nj++) {
                uint32_t r[4];
                ldsm4t(r, vsb + ((kb + lrow) * FSTR + nj * 16 + lk) * 2);
                uint32_t bf0[2] = { r[0], r[1] };
                uint32_t bf1[2] = { r[2], r[3] };
                mma_f16(accO[2*nj],   af, bf0);
                mma_f16(accO[2*nj+1], af, bf1);
            }
        }
    }

    float i0 = 1.f / lr0, i1 = 1.f / lr1;
    #pragma unroll
    for (int ni = 0; ni < 8; ni++) {
        int d = ni * 8 + 2 * t;
        *(__half2*)(o + (size_t)(b * TT + q0 + r0) * EE + h * 64 + d) =
            __floats2half2_rn(accO[ni][0] * i0, accO[ni][1] * i0);
        *(__half2*)(o + (size_t)(b * TT + q0 + r0 + 8) * EE + h * 64 + d) =
            __floats2half2_rn(accO[ni][2] * i1, accO[ni][3] * i1);
    }
}

// ---------------- loss: merge per-segment partials ----------------
__global__ void loss_merge_kernel(const float2* __restrict__ part,
                                  const float* __restrict__ logits,
                                  const int* __restrict__ targets,
                                  float* __restrict__ rowloss)
{
    int row = blockIdx.x, tid = threadIdx.x;  // 128 threads
    const float2* pr = part + (size_t)row * NSEG;
    float m = -1e30f, s = 0.f;
    for (int i = tid; i < NSEG; i += 128) {
        float2 p = pr[i];
        float M = fmaxf(m, p.x);
        s = s * mexp(m - M) + p.y * mexp(p.x - M);
        m = M;
    }
    #pragma unroll
    for (int o = 16; o; o >>= 1) {
        float m2 = __shfl_xor_sync(0xffffffffu, m, o);
        float s2 = __shfl_xor_sync(0xffffffffu, s, o);
        float M = fmaxf(m, m2);
        s = s * mexp(m - M) + s2 * mexp(m2 - M);
        m = M;
    }
    __shared__ float sm_[4], ss_[4];
    int w = tid >> 5;
    if ((tid & 31) == 0) { sm_[w] = m; ss_[w] = s; }
    __syncthreads();
    if (tid == 0) {
        m = sm_[0]; s = ss_[0];
        for (int i = 1; i < 4; i++) {
            float M = fmaxf(m, sm_[i]);
            s = s * mexp(m - M) + ss_[i] * mexp(sm_[i] - M);
            m = M;
        }
        float lse = m + logf(s);
        rowloss[row] = lse - logits[(size_t)row * VV + targets[row]];
    }
}

__global__ void loss_reduce_kernel(const float* __restrict__ rowloss, float* __restrict__ out)
{
    __shared__ float red[256];
    int tid = threadIdx.x;
    float s = 0.f;
    for (int i = tid; i < MROWS; i += 256) s += rowloss[i];
    red[tid] = s; __syncthreads();
    for (int o = 128; o > 0; o >>= 1) { if (tid < o) red[tid] += red[tid + o]; __syncthreads(); }
    if (tid == 0) out[0] = red[0] * (1.0f / MROWS);
}

// ---------------- host orchestration ----------------
#define SMEMG (NSTG * (ASZH + BSZH) * 2)   // 75776
#define SMEMF (5 * FTSZ * 2)               // 46080

extern "C" void kernel_launch(void* const* d_in, const int* in_sizes, int n_in,
                              void* d_out, int out_size)
{
    const int*   ctx  = (const int*)  d_in[0];
    const int*   tgt  = (const int*)  d_in[1];
    const float* tok  = (const float*)d_in[2];
    const float* pos  = (const float*)d_in[3];
    const float* Wq   = (const float*)d_in[4];
    const float* Wk   = (const float*)d_in[5];
    const float* Wv   = (const float*)d_in[6];
    const float* Wo   = (const float*)d_in[7];
    const float* bo   = (const float*)d_in[8];
    const float* ln1g = (const float*)d_in[9];
    const float* ln1b = (const float*)d_in[10];
    const float* ln2g = (const float*)d_in[11];
    const float* ln2b = (const float*)d_in[12];
    const float* W1   = (const float*)d_in[13];
    const float* b1   = (const float*)d_in[14];
    const float* W2   = (const float*)d_in[15];
    const float* b2   = (const float*)d_in[16];
    const float* lnfg = (const float*)d_in[17];
    const float* lnfb = (const float*)d_in[18];
    const float* Wlm  = (const float*)d_in[19];
    const float* blm  = (const float*)d_in[20];

    static float *px = nullptr, *prl;
    static float2 *plp;
    static __half *ph, *pq, *pk, *pv, *po, *pff;
    static __half *whq, *whk, *whv, *who, *wh1, *wh2, *whlm;
    static cudaStream_t s2;
    static cudaEvent_t evFork, evQ[LL], evW[LL], evLM;
    if (!px) {
        cudaGetSymbolAddress((void**)&px,  g_x);
        cudaGetSymbolAddress((void**)&prl, g_rowloss);
        cudaGetSymbolAddress((void**)&plp, g_lpart);
        cudaGetSymbolAddress((void**)&ph,  g_h);
        cudaGetSymbolAddress((void**)&pq,  g_q);
        cudaGetSymbolAddress((void**)&pk,  g_k);
        cudaGetSymbolAddress((void**)&pv,  g_v);
        cudaGetSymbolAddress((void**)&po,  g_o);
        cudaGetSymbolAddress((void**)&pff, g_ff);
        cudaGetSymbolAddress((void**)&whq, g_whq);
        cudaGetSymbolAddress((void**)&whk, g_whk);
        cudaGetSymbolAddress((void**)&whv, g_whv);
        cudaGetSymbolAddress((void**)&who, g_who);
        cudaGetSymbolAddress((void**)&wh1, g_wh1);
        cudaGetSymbolAddress((void**)&wh2, g_wh2);
        cudaGetSymbolAddress((void**)&whlm, g_whlm);
        cudaFuncSetAttribute(hgemm_kernel,    cudaFuncAttributeMaxDynamicSharedMemorySize, SMEMG);
        cudaFuncSetAttribute(hgemm_lm_kernel, cudaFuncAttributeMaxDynamicSharedMemorySize, SMEMG);
        cudaFuncSetAttribute(flash_kernel,    cudaFuncAttributeMaxDynamicSharedMemorySize, SMEMF);
        int loPr, hiPr;
        cudaDeviceGetStreamPriorityRange(&loPr, &hiPr);
        cudaStreamCreateWithPriority(&s2, cudaStreamNonBlocking, loPr);
        cudaEventCreateWithFlags(&evFork, cudaEventDisableTiming);
        for (int l = 0; l < LL; l++) {
            cudaEventCreateWithFlags(&evQ[l], cudaEventDisableTiming);
            cudaEventCreateWithFlags(&evW[l], cudaEventDisableTiming);
        }
        cudaEventCreateWithFlags(&evLM, cudaEventDisableTiming);
    }
    float* out = (float*)d_out;

    // ---- fork low-priority side stream; convert weights per-layer, QKV first ----
    cudaEventRecord(evFork, 0);
    cudaStreamWaitEvent(s2, evFork, 0);
    const int EEE8 = EE * EE / 8, EFF8 = EE * FF_ / 8;
    for (int l = 0; l < LL; l++) {
        size_t oE = (size_t)l * EE * EE, oF = (size_t)l * EE * FF_;
        conv_h2<<<512,  256, 0, s2>>>((const float4*)(Wq + oE), (uint4*)(whq + oE), EEE8);
        conv_h2<<<512,  256, 0, s2>>>((const float4*)(Wk + oE), (uint4*)(whk + oE), EEE8);
        conv_h2<<<512,  256, 0, s2>>>((const float4*)(Wv + oE), (uint4*)(whv + oE), EEE8);
        cudaEventRecord(evQ[l], s2);
        conv_h2<<<512,  256, 0, s2>>>((const float4*)(Wo + oE), (uint4*)(who + oE), EEE8);
        conv_h2<<<2048, 256, 0, s2>>>((const float4*)(W1 + oF), (uint4*)(wh1 + oF), EFF8);
        conv_h2<<<2048, 256, 0, s2>>>((const float4*)(W2 + oF), (uint4*)(wh2 + oF), EFF8);
        cudaEventRecord(evW[l], s2);
    }
    conv_h2<<<8192, 256, 0, s2>>>((const float4*)Wlm, (uint4*)whlm, EE * VV / 8);
    cudaEventRecord(evLM, s2);

    embed_kernel<<<MROWS, 256>>>(ctx, tok, pos, px);

    dim3 gQKV(16, 24);
    dim3 gEo (16, 8);
    dim3 gF1 (16, 32);
    dim3 gLM (16, 250);
    dim3 gFA (32, 16);
    int gLN = MROWS / 8;

    for (int l = 0; l < LL; l++) {
        size_t oE = (size_t)l * EE * EE, oF = (size_t)l * EE * FF_;

        ln_kernel<<<gLN, 256>>>(px, ln1g + l * EE, ln1b + l * EE, ph);

        cudaStreamWaitEvent(0, evQ[l], 0);
        hgemm_kernel<<<gQKV, 256, SMEMG>>>(ph, whq + oE, whk + oE, whv + oE, EE,
                                           nullptr, nullptr, pq, pk, pv, EE, 0, 1, 1);

        flash_kernel<<<gFA, 128, SMEMF>>>(pq, pk, pv, po);

        cudaStreamWaitEvent(0, evW[l], 0);
        hgemm_kernel<<<gEo, 256, SMEMG>>>(po, who + oE, who + oE, who + oE, EE,
                                          bo + l * EE, px, px, px, px, EE, 0, 0, 0);

        ln_kernel<<<gLN, 256>>>(px, ln2g + l * EE, ln2b + l * EE, ph);

        hgemm_kernel<<<gF1, 256, SMEMG>>>(ph, wh1 + oF, wh1 + oF, wh1 + oF, FF_,
                                          b1 + l * FF_, nullptr, pff, pff, pff, EE, 1, 1, 0);

        hgemm_kernel<<<gEo, 256, SMEMG>>>(pff, wh2 + oF, wh2 + oF, wh2 + oF, EE,
                                          b2 + l * EE, px, px, px, px, FF_, 0, 0, 0);
    }

    cudaStreamWaitEvent(0, evLM, 0);
    ln_kernel<<<gLN, 256>>>(px, lnfg, lnfb, ph);
    hgemm_lm_kernel<<<gLM, 256, SMEMG>>>(ph, whlm, blm, out, EE);

    if (out_size > MROWS * VV) {
        loss_merge_kernel<<<MROWS, 128>>>(plp, out, tgt, prl);
        loss_reduce_kernel<<<1, 256>>>(prl, out + (size_t)MROWS * VV);
    }
}